// round 3
// baseline (speedup 1.0000x reference)
#include <cuda_runtime.h>
#include <math.h>

typedef unsigned long long ULL;

// ---------------- static scratch (no allocations allowed) ----------------
__device__ __align__(16) float g_v[2 * 1024 * 64];      // vertex feats [B,N,64]
__device__ __align__(16) float g_f[2 * 2048 * 64];      // face feats   [B,F,64]
__device__ __align__(16) float g_X[2 * 4096 * 16];      // x buffer (= [B,N,64])
__device__ __align__(16) float g_Y[2 * 8192 * 16];      // y buffer (= [B,F,64])
__device__ __align__(16) float g_part[1048576];         // split-K partials (4 MB)
__device__ float g_sp[64 * 64];
__device__ float g_sq[64 * 64];
__device__ float g_a[64];
__device__ float g_c[64];
__device__ float g_pool[2 * 64];

// ---------------- helpers ----------------
__device__ __forceinline__ float elu1(float x) { return x > 0.f ? x : expm1f(x); }

__device__ __forceinline__ ULL pk2(float s) {
    ULL r; asm("mov.b64 %0, {%1, %1};" : "=l"(r) : "f"(s)); return r;
}
__device__ __forceinline__ void fma2(ULL& d, ULL a, ULL b) {
    asm("fma.rn.f32x2 %0, %1, %2, %0;" : "+l"(d) : "l"(a), "l"(b));
}
__device__ __forceinline__ void cpa16(unsigned dst, const float* src) {
    asm volatile("cp.async.cg.shared.global [%0], [%1], 16;" :: "r"(dst), "l"(src));
}

// ---------------- init kernels ----------------
__global__ void k_init_v(const float* __restrict__ inp,
                         const float* __restrict__ Win,
                         const float* __restrict__ bin,
                         float* __restrict__ v) {
    int idx = blockIdx.x * 256 + threadIdx.x;          // 2048*64 = 131072
    int r = idx >> 6, ch = idx & 63;
    float acc = bin[ch];
#pragma unroll
    for (int k = 0; k < 3; k++) acc = fmaf(inp[r * 3 + k], Win[k * 64 + ch], acc);
    v[idx] = acc;
}

__global__ void k_zero(float* __restrict__ p, int n) {
    int i = blockIdx.x * 256 + threadIdx.x;
    if (i < n) p[i] = 0.f;
}

// ---------------- BN stats (two-phase, deterministic) ----------------
__global__ void k_stats_part(const float* __restrict__ src, int rows) {
    __shared__ float ss[256], qq[256];
    int ch = threadIdx.x & 63, g = threadIdx.x >> 6;
    int slice = rows / gridDim.x;                       // gridDim.x = 64
    int r0 = blockIdx.x * slice;
    float s = 0.f, q = 0.f;
    for (int r = r0 + g; r < r0 + slice; r += 4) {
        float x = elu1(src[(size_t)r * 64 + ch]);
        s += x; q += x * x;
    }
    ss[threadIdx.x] = s; qq[threadIdx.x] = q;
    __syncthreads();
    if (g == 0) {
#pragma unroll
        for (int j = 1; j < 4; j++) { s += ss[ch + 64 * j]; q += qq[ch + 64 * j]; }
        g_sp[blockIdx.x * 64 + ch] = s;
        g_sq[blockIdx.x * 64 + ch] = q;
    }
}

__global__ void k_stats_final(const float* __restrict__ gamma,
                              const float* __restrict__ beta, float inv_count) {
    int ch = threadIdx.x;                               // 64 threads
    float s = 0.f, q = 0.f;
    for (int i = 0; i < 64; i++) { s += g_sp[i * 64 + ch]; q += g_sq[i * 64 + ch]; }
    float m = s * inv_count;
    float var = q * inv_count - m * m;
    float a = gamma[ch] * rsqrtf(var + 1e-5f);
    g_a[ch] = a;
    g_c[ch] = beta[ch] - m * a;
}

// ---------------- elu -> BN -> 64x64 linear -> elu ----------------
__global__ void __launch_bounds__(256) k_xform(const float* __restrict__ src,
                                               const float* __restrict__ W,
                                               const float* __restrict__ bias,
                                               float* __restrict__ dst, int rows) {
    __shared__ float Ws[64 * 64];
    __shared__ float ts[4 * 64];
    __shared__ float sa[64], sc[64], sb[64];
    for (int i = threadIdx.x; i < 4096; i += 256) Ws[i] = W[i];
    if (threadIdx.x < 64) {
        sa[threadIdx.x] = g_a[threadIdx.x];
        sc[threadIdx.x] = g_c[threadIdx.x];
        sb[threadIdx.x] = bias[threadIdx.x];
    }
    __syncthreads();
    int ch = threadIdx.x & 63, g = threadIdx.x >> 6;
    int rpb = rows / gridDim.x;                         // 16
    int base = blockIdx.x * rpb;
    for (int t = 0; t < rpb / 4; t++) {
        int r = base + t * 4 + g;
        float x = elu1(src[(size_t)r * 64 + ch]);
        ts[g * 64 + ch] = fmaf(x, sa[ch], sc[ch]);
        __syncthreads();
        float acc = sb[ch];
#pragma unroll
        for (int k = 0; k < 64; k++) acc = fmaf(ts[g * 64 + k], Ws[k * 64 + ch], acc);
        dst[(size_t)r * 64 + ch] = elu1(acc);
        __syncthreads();
    }
}

// ---------------- skinny GEMM: part[slice] = D[128-row tile, K-slice] @ X ----------------
// grid (ksplit, M/128, B), block 128. Coalesced cp.async staging of D into a
// swizzled smem tile (row stride 20 floats, 16B-quad XOR swizzle by (r>>3)&3 —
// conflict-free scalar row reads). X chunks broadcast from smem. Double-buffered.
__global__ void __launch_bounds__(128) k_gemm(const float* __restrict__ D,
                                              const float* __restrict__ X,
                                              float* __restrict__ part,
                                              int M, int K) {
    __shared__ __align__(16) float Ds[2][128 * 20];     // 20 KB
    __shared__ __align__(16) float Xs[2][16 * 16];      // 2 KB
    int tid = threadIdx.x;
    int ksplit = gridDim.x;
    int Kslice = K / ksplit;                            // 2048
    int nchunk = Kslice / 16;                           // 128
    int slice = blockIdx.x, mt = blockIdx.y, b = blockIdx.z;
    const float* Dg = D + ((size_t)b * M + (size_t)mt * 128) * K + (size_t)slice * Kslice;
    const float* Xg = X + ((size_t)b * K + (size_t)slice * Kslice) * 16;

    int rq = tid >> 2, qi = tid & 3;                    // staging: 32 rows x 4 quads per pass

    auto stage = [&](int c, int buf) {
        const float* dsrc = Dg + c * 16 + qi * 4;
#pragma unroll
        for (int rg = 0; rg < 4; rg++) {
            int r = rg * 32 + rq;
            int sw = (r >> 3) & 3;
            unsigned dst = (unsigned)__cvta_generic_to_shared(
                &Ds[buf][r * 20 + 4 * (qi ^ sw)]);
            cpa16(dst, dsrc + (size_t)r * K);
        }
        if (tid < 64) {
            unsigned dst = (unsigned)__cvta_generic_to_shared(&Xs[buf][tid * 4]);
            cpa16(dst, Xg + c * 256 + tid * 4);
        }
    };

    ULL acc[8];
#pragma unroll
    for (int j = 0; j < 8; j++) acc[j] = 0ULL;

    int r = tid;                                        // compute: one row per thread
    int sw = (r >> 3) & 3;

    stage(0, 0);
    asm volatile("cp.async.commit_group;");

    for (int c = 0; c < nchunk; c++) {
        if (c + 1 < nchunk) stage(c + 1, (c + 1) & 1);
        asm volatile("cp.async.commit_group;");
        asm volatile("cp.async.wait_group 1;");
        __syncthreads();
        const float* dr = &Ds[c & 1][r * 20];
        const ulonglong2* xr = (const ulonglong2*)Xs[c & 1];
#pragma unroll 4
        for (int k = 0; k < 16; k++) {
            float dv = dr[4 * ((k >> 2) ^ sw) + (k & 3)];
            ULL w = pk2(dv);
#pragma unroll
            for (int j = 0; j < 4; j++) {
                ulonglong2 xv = xr[k * 4 + j];
                fma2(acc[2 * j],     w, xv.x);
                fma2(acc[2 * j + 1], w, xv.y);
            }
        }
        __syncthreads();
    }

    ulonglong2* op = (ulonglong2*)(part +
        (((size_t)slice * gridDim.z + b) * M + (size_t)mt * 128 + r) * 16);
#pragma unroll
    for (int j = 0; j < 4; j++) {
        ulonglong2 t; t.x = acc[2 * j]; t.y = acc[2 * j + 1];
        op[j] = t;
    }
}

// deterministic ordered split-K reduce:  out[i] += sum_s part[s][i]
__global__ void k_reduce(float4* __restrict__ out, const float4* __restrict__ part,
                         int n4, int ksplit) {
    int i = blockIdx.x * 256 + threadIdx.x;
    if (i >= n4) return;
    float4 a = out[i];
    for (int s = 0; s < ksplit; s++) {
        float4 p = part[(size_t)s * n4 + i];
        a.x += p.x; a.y += p.y; a.z += p.z; a.w += p.w;
    }
    out[i] = a;
}

// ---------------- epilogue ----------------
__global__ void k_pool(const float* __restrict__ t, const float* __restrict__ mask) {
    __shared__ float ss[256], ms[256];
    int b = blockIdx.x;
    int ch = threadIdx.x & 63, g = threadIdx.x >> 6;
    float s = 0.f, m = 0.f;
    for (int n = g; n < 1024; n += 4) {
        float mv = mask[b * 1024 + n];
        s += t[((size_t)b * 1024 + n) * 64 + ch] * mv;
        m += mv;
    }
    ss[threadIdx.x] = s; ms[threadIdx.x] = m;
    __syncthreads();
    if (g == 0) {
#pragma unroll
        for (int j = 1; j < 4; j++) { s += ss[ch + 64 * j]; m += ms[ch + 64 * j]; }
        g_pool[b * 64 + ch] = s / m;
    }
}

__global__ void k_head(const float* __restrict__ Wfc, const float* __restrict__ bfc,
                       float* __restrict__ out) {
    __shared__ float lg[2][10];
    int tid = threadIdx.x;
    if (tid < 20) {
        int b = tid / 10, j = tid % 10;
        float acc = bfc[j];
        for (int ch = 0; ch < 64; ch++) acc = fmaf(g_pool[b * 64 + ch], Wfc[ch * 10 + j], acc);
        lg[b][j] = acc;
    }
    __syncthreads();
    if (tid < 20) {
        int b = tid / 10, j = tid % 10;
        float mx = -1e30f;
        for (int t = 0; t < 10; t++) mx = fmaxf(mx, lg[b][t]);
        float se = 0.f;
        for (int t = 0; t < 10; t++) se += expf(lg[b][t] - mx);
        out[b * 10 + j] = lg[b][j] - mx - logf(se);
    }
}

// ---------------- launcher ----------------
extern "C" void kernel_launch(void* const* d_in, const int* in_sizes, int n_in,
                              void* d_out, int out_size) {
    const float* inp  = (const float*)d_in[0];
    const float* Di   = (const float*)d_in[1];
    const float* DiA  = (const float*)d_in[2];
    const float* mask = (const float*)d_in[3];
    const float* W_in = (const float*)d_in[4];
    const float* b_in = (const float*)d_in[5];
    const float* rnW0 = (const float*)d_in[6];
    const float* rnb0 = (const float*)d_in[7];
    const float* rng0 = (const float*)d_in[8];
    const float* rnbe0= (const float*)d_in[9];
    const float* rnW1 = (const float*)d_in[10];
    const float* rnb1 = (const float*)d_in[11];
    const float* rng1 = (const float*)d_in[12];
    const float* rnbe1= (const float*)d_in[13];
    const float* bn2g = (const float*)d_in[14];
    const float* bn2b = (const float*)d_in[15];
    const float* W2   = (const float*)d_in[16];
    const float* b2   = (const float*)d_in[17];
    const float* Wfc  = (const float*)d_in[18];
    const float* bfc  = (const float*)d_in[19];
    float* out = (float*)d_out;

    float *v, *f, *X, *Y, *part;
    cudaGetSymbolAddress((void**)&v, g_v);
    cudaGetSymbolAddress((void**)&f, g_f);
    cudaGetSymbolAddress((void**)&X, g_X);
    cudaGetSymbolAddress((void**)&Y, g_Y);
    cudaGetSymbolAddress((void**)&part, g_part);

    k_init_v<<<512, 256>>>(inp, W_in, b_in, v);
    k_zero<<<1024, 256>>>(f, 2 * 2048 * 64);

    for (int i = 0; i < 5; i++) {
        // vertex -> face
        k_stats_part<<<64, 256>>>(v, 2048);
        k_stats_final<<<1, 64>>>(rng0 + i * 64, rnbe0 + i * 64, 1.f / 2048.f);
        k_xform<<<128, 256>>>(v, rnW0 + i * 4096, rnb0 + i * 64, X, 2048);
        k_gemm<<<dim3(2, 64, 2), 128>>>(Di, X, part, 8192, 4096);
        k_reduce<<<256, 256>>>((float4*)f, (const float4*)part, 65536, 2);
        // face -> vertex
        k_stats_part<<<64, 256>>>(f, 4096);
        k_stats_final<<<1, 64>>>(rng1 + i * 64, rnbe1 + i * 64, 1.f / 4096.f);
        k_xform<<<256, 256>>>(f, rnW1 + i * 4096, rnb1 + i * 64, Y, 4096);
        k_gemm<<<dim3(4, 32, 2), 128>>>(DiA, Y, part, 4096, 8192);
        k_reduce<<<128, 256>>>((float4*)v, (const float4*)part, 32768, 4);
    }

    // epilogue: elu -> BN -> W2 -> elu -> masked mean pool -> fc -> log_softmax
    k_stats_part<<<64, 256>>>(v, 2048);
    k_stats_final<<<1, 64>>>(bn2g, bn2b, 1.f / 2048.f);
    k_xform<<<128, 256>>>(v, W2, b2, Y, 2048);
    k_pool<<<2, 256>>>(Y, mask);
    k_head<<<1, 32>>>(Wfc, bfc, out);
}

// round 4
// speedup vs baseline: 1.2620x; 1.2620x over previous
#include <cuda_runtime.h>
#include <math.h>

typedef unsigned long long ULL;

// ---------------- static scratch (no allocations allowed) ----------------
__device__ __align__(16) float g_v[2 * 1024 * 64];      // vertex feats [B,N,64]
__device__ __align__(16) float g_f[2 * 2048 * 64];      // face feats   [B,F,64]
__device__ __align__(16) float g_X[2 * 4096 * 16];      // x buffer
__device__ __align__(16) float g_Y[2 * 8192 * 16];      // y buffer
__device__ __align__(16) float g_part[4194304];         // split-K partials (16 MB)
__device__ float g_sp[256 * 64];
__device__ float g_sq[256 * 64];
__device__ float g_a[64];
__device__ float g_c[64];
__device__ float g_pool[2 * 64];

// ---------------- helpers ----------------
__device__ __forceinline__ float elu1(float x) { return x > 0.f ? x : expm1f(x); }

__device__ __forceinline__ ULL pk2(float s) {
    ULL r; asm("mov.b64 %0, {%1, %1};" : "=l"(r) : "f"(s)); return r;
}
__device__ __forceinline__ void fma2(ULL& d, ULL a, ULL b) {
    asm("fma.rn.f32x2 %0, %1, %2, %0;" : "+l"(d) : "l"(a), "l"(b));
}

// ---------------- init: v = inp@Win + b, fused elu-stats partials ----------------
__global__ void __launch_bounds__(256) k_init_v(const float* __restrict__ inp,
                                                const float* __restrict__ Win,
                                                const float* __restrict__ bin) {
    __shared__ float ss[256], qq[256];
    int tid = threadIdx.x, ch = tid & 63;
    float b = bin[ch], w0 = Win[ch], w1 = Win[64 + ch], w2 = Win[128 + ch];
    float s = 0.f, q = 0.f;
#pragma unroll
    for (int e = 0; e < 2; e++) {
        int idx = e * 65536 + blockIdx.x * 256 + tid;    // 256 blocks cover 131072
        int r = idx >> 6;
        float acc = fmaf(inp[r * 3 + 2], w2, fmaf(inp[r * 3 + 1], w1, fmaf(inp[r * 3], w0, b)));
        g_v[idx] = acc;
        float x = elu1(acc); s += x; q += x * x;
    }
    ss[tid] = s; qq[tid] = q;
    __syncthreads();
    if (tid < 64) {
#pragma unroll
        for (int j = 1; j < 4; j++) { s += ss[tid + 64 * j]; q += qq[tid + 64 * j]; }
        g_sp[blockIdx.x * 64 + tid] = s;
        g_sq[blockIdx.x * 64 + tid] = q;
    }
}

__global__ void k_zero(float* __restrict__ p, int n) {
    int i = blockIdx.x * 256 + threadIdx.x;
    if (i < n) p[i] = 0.f;
}

// ---------------- finalize BN coefficients ----------------
__global__ void __launch_bounds__(256) k_stats_final(const float* __restrict__ gamma,
                                                     const float* __restrict__ beta,
                                                     float invc, int nblk) {
    __shared__ float ss[256], qq[256];
    int tid = threadIdx.x, ch = tid & 63, grp = tid >> 6;
    float s = 0.f, q = 0.f;
    for (int i = grp; i < nblk; i += 4) { s += g_sp[i * 64 + ch]; q += g_sq[i * 64 + ch]; }
    ss[tid] = s; qq[tid] = q;
    __syncthreads();
    if (tid < 64) {
#pragma unroll
        for (int j = 1; j < 4; j++) { s += ss[tid + 64 * j]; q += qq[tid + 64 * j]; }
        float m = s * invc;
        float var = q * invc - m * m;
        float a = gamma[tid] * rsqrtf(var + 1e-5f);
        g_a[tid] = a;
        g_c[tid] = beta[tid] - m * a;
    }
}

// ---------------- elu -> BN -> 64x64 linear -> elu ----------------
__global__ void __launch_bounds__(256) k_xform(const float* __restrict__ src,
                                               const float* __restrict__ W,
                                               const float* __restrict__ bias,
                                               float* __restrict__ dst, int rows) {
    __shared__ float Ws[64 * 64];
    __shared__ float ts[4 * 64];
    __shared__ float sa[64], sc[64], sb[64];
    for (int i = threadIdx.x; i < 4096; i += 256) Ws[i] = W[i];
    if (threadIdx.x < 64) {
        sa[threadIdx.x] = g_a[threadIdx.x];
        sc[threadIdx.x] = g_c[threadIdx.x];
        sb[threadIdx.x] = bias[threadIdx.x];
    }
    __syncthreads();
    int ch = threadIdx.x & 63, g = threadIdx.x >> 6;
    int rpb = rows / gridDim.x;                          // 16
    int base = blockIdx.x * rpb;
    for (int t = 0; t < rpb / 4; t++) {
        int r = base + t * 4 + g;
        float x = elu1(src[(size_t)r * 64 + ch]);
        ts[g * 64 + ch] = fmaf(x, sa[ch], sc[ch]);
        __syncthreads();
        float acc = sb[ch];
#pragma unroll
        for (int k = 0; k < 64; k++) acc = fmaf(ts[g * 64 + k], Ws[k * 64 + ch], acc);
        dst[(size_t)r * 64 + ch] = elu1(acc);
        __syncthreads();
    }
}

// ---------------- skinny GEMM: part[slice] = D[512-row tile, K-slice] @ X ----------------
// grid (ksplit, M/512, B), block 128. 4 rows/thread. Register-pipelined LDG,
// k-major smem staging (513-float stride -> conflict-free per-k row reads),
// X broadcast from smem, one __syncthreads per 8-k chunk.
__global__ void __launch_bounds__(128) k_gemm(const float* __restrict__ D,
                                              const float* __restrict__ X,
                                              float* __restrict__ part,
                                              int M, int K) {
    __shared__ __align__(16) float Ds[2][8 * 513];       // 32.8 KB
    __shared__ __align__(16) float Xs[2][8 * 16];        // 1 KB
    int tid = threadIdx.x;
    int slice = blockIdx.x, mt = blockIdx.y, b = blockIdx.z;
    int Kslice = K / gridDim.x;                          // 256
    int nchunk = Kslice >> 3;                            // 32
    const float* Dg = D + ((size_t)b * M + (size_t)mt * 512) * K + (size_t)slice * Kslice;
    const float* Xg = X + ((size_t)b * K + (size_t)slice * Kslice) * 16;

    float4 st[8];
    float4 xst = make_float4(0.f, 0.f, 0.f, 0.f);

    ULL acc[4][8];
#pragma unroll
    for (int j = 0; j < 4; j++)
#pragma unroll
        for (int q = 0; q < 8; q++) acc[j][q] = 0ULL;

    // ---- prologue: load + stage chunk 0 ----
#pragma unroll
    for (int j = 0; j < 8; j++) {
        int i = tid + 128 * j;
        int row = i >> 1, half = i & 1;
        st[j] = *(const float4*)(Dg + (size_t)row * K + half * 4);
    }
    if (tid < 32) xst = *(const float4*)(Xg + tid * 4);
#pragma unroll
    for (int j = 0; j < 8; j++) {
        int i = tid + 128 * j;
        int row = i >> 1, half = i & 1;
        Ds[0][(half * 4 + 0) * 513 + row] = st[j].x;
        Ds[0][(half * 4 + 1) * 513 + row] = st[j].y;
        Ds[0][(half * 4 + 2) * 513 + row] = st[j].z;
        Ds[0][(half * 4 + 3) * 513 + row] = st[j].w;
    }
    if (tid < 32) *(float4*)&Xs[0][tid * 4] = xst;
    __syncthreads();

    for (int c = 0; c < nchunk; c++) {
        // issue next chunk's global loads (latency hidden under compute)
        if (c + 1 < nchunk) {
#pragma unroll
            for (int j = 0; j < 8; j++) {
                int i = tid + 128 * j;
                int row = i >> 1, half = i & 1;
                st[j] = *(const float4*)(Dg + (size_t)row * K + (c + 1) * 8 + half * 4);
            }
            if (tid < 32) xst = *(const float4*)(Xg + (c + 1) * 128 + tid * 4);
        }
        // compute chunk c
        int buf = c & 1;
#pragma unroll
        for (int kk = 0; kk < 8; kk++) {
            const ULL* xr = (const ULL*)&Xs[buf][kk * 16];
            ULL xv[8];
#pragma unroll
            for (int q = 0; q < 8; q++) xv[q] = xr[q];
#pragma unroll
            for (int j = 0; j < 4; j++) {
                float dv = Ds[buf][kk * 513 + 128 * j + tid];
                ULL w = pk2(dv);
#pragma unroll
                for (int q = 0; q < 8; q++) fma2(acc[j][q], w, xv[q]);
            }
        }
        // stage chunk c+1 into the other buffer (no race: compute(c-1) ended
        // before the previous iteration's barrier)
        if (c + 1 < nchunk) {
            int nb = buf ^ 1;
#pragma unroll
            for (int j = 0; j < 8; j++) {
                int i = tid + 128 * j;
                int row = i >> 1, half = i & 1;
                Ds[nb][(half * 4 + 0) * 513 + row] = st[j].x;
                Ds[nb][(half * 4 + 1) * 513 + row] = st[j].y;
                Ds[nb][(half * 4 + 2) * 513 + row] = st[j].z;
                Ds[nb][(half * 4 + 3) * 513 + row] = st[j].w;
            }
            if (tid < 32) *(float4*)&Xs[nb][tid * 4] = xst;
            __syncthreads();
        }
    }

    size_t obase = ((size_t)slice * gridDim.z + b) * M + (size_t)mt * 512;
#pragma unroll
    for (int j = 0; j < 4; j++) {
        ulonglong2* op = (ulonglong2*)(part + (obase + 128 * j + tid) * 16);
#pragma unroll
        for (int q = 0; q < 4; q++) {
            ulonglong2 t; t.x = acc[j][2 * q]; t.y = acc[j][2 * q + 1];
            op[q] = t;
        }
    }
}

// ---------------- split-K reduce + fused elu-stats partials ----------------
__global__ void __launch_bounds__(256) k_reduce(float4* __restrict__ out,
                                                const float4* __restrict__ part,
                                                int n4, int ksplit) {
    __shared__ float ss[256 * 4], qq[256 * 4];
    int tid = threadIdx.x;
    int i = blockIdx.x * 256 + tid;
    float4 a = out[i];
    for (int s = 0; s < ksplit; s++) {
        float4 p = part[(size_t)s * n4 + i];
        a.x += p.x; a.y += p.y; a.z += p.z; a.w += p.w;
    }
    out[i] = a;
    float e0 = elu1(a.x), e1 = elu1(a.y), e2 = elu1(a.z), e3 = elu1(a.w);
    ss[tid * 4 + 0] = e0; qq[tid * 4 + 0] = e0 * e0;
    ss[tid * 4 + 1] = e1; qq[tid * 4 + 1] = e1 * e1;
    ss[tid * 4 + 2] = e2; qq[tid * 4 + 2] = e2 * e2;
    ss[tid * 4 + 3] = e3; qq[tid * 4 + 3] = e3 * e3;
    __syncthreads();
    if (tid < 64) {
        int g = tid >> 2, e = tid & 3;                  // channel = 4*g + e
        float s = 0.f, q = 0.f;
#pragma unroll
        for (int m = 0; m < 16; m++) {
            int t = g + 16 * m;
            s += ss[t * 4 + e]; q += qq[t * 4 + e];
        }
        g_sp[blockIdx.x * 64 + tid] = s;
        g_sq[blockIdx.x * 64 + tid] = q;
    }
}

// ---------------- epilogue ----------------
__global__ void k_pool(const float* __restrict__ t, const float* __restrict__ mask) {
    __shared__ float ss[256], ms[256];
    int b = blockIdx.x;
    int ch = threadIdx.x & 63, g = threadIdx.x >> 6;
    float s = 0.f, m = 0.f;
    for (int n = g; n < 1024; n += 4) {
        float mv = mask[b * 1024 + n];
        s += t[((size_t)b * 1024 + n) * 64 + ch] * mv;
        m += mv;
    }
    ss[threadIdx.x] = s; ms[threadIdx.x] = m;
    __syncthreads();
    if (g == 0) {
#pragma unroll
        for (int j = 1; j < 4; j++) { s += ss[ch + 64 * j]; m += ms[ch + 64 * j]; }
        g_pool[b * 64 + ch] = s / m;
    }
}

__global__ void k_head(const float* __restrict__ Wfc, const float* __restrict__ bfc,
                       float* __restrict__ out) {
    __shared__ float lg[2][10];
    int tid = threadIdx.x;
    if (tid < 20) {
        int b = tid / 10, j = tid % 10;
        float acc = bfc[j];
        for (int ch = 0; ch < 64; ch++) acc = fmaf(g_pool[b * 64 + ch], Wfc[ch * 10 + j], acc);
        lg[b][j] = acc;
    }
    __syncthreads();
    if (tid < 20) {
        int b = tid / 10, j = tid % 10;
        float mx = -1e30f;
        for (int t = 0; t < 10; t++) mx = fmaxf(mx, lg[b][t]);
        float se = 0.f;
        for (int t = 0; t < 10; t++) se += expf(lg[b][t] - mx);
        out[b * 10 + j] = lg[b][j] - mx - logf(se);
    }
}

// ---------------- launcher ----------------
extern "C" void kernel_launch(void* const* d_in, const int* in_sizes, int n_in,
                              void* d_out, int out_size) {
    const float* inp  = (const float*)d_in[0];
    const float* Di   = (const float*)d_in[1];
    const float* DiA  = (const float*)d_in[2];
    const float* mask = (const float*)d_in[3];
    const float* W_in = (const float*)d_in[4];
    const float* b_in = (const float*)d_in[5];
    const float* rnW0 = (const float*)d_in[6];
    const float* rnb0 = (const float*)d_in[7];
    const float* rng0 = (const float*)d_in[8];
    const float* rnbe0= (const float*)d_in[9];
    const float* rnW1 = (const float*)d_in[10];
    const float* rnb1 = (const float*)d_in[11];
    const float* rng1 = (const float*)d_in[12];
    const float* rnbe1= (const float*)d_in[13];
    const float* bn2g = (const float*)d_in[14];
    const float* bn2b = (const float*)d_in[15];
    const float* W2   = (const float*)d_in[16];
    const float* b2   = (const float*)d_in[17];
    const float* Wfc  = (const float*)d_in[18];
    const float* bfc  = (const float*)d_in[19];
    float* out = (float*)d_out;

    float *v, *f, *X, *Y, *part;
    cudaGetSymbolAddress((void**)&v, g_v);
    cudaGetSymbolAddress((void**)&f, g_f);
    cudaGetSymbolAddress((void**)&X, g_X);
    cudaGetSymbolAddress((void**)&Y, g_Y);
    cudaGetSymbolAddress((void**)&part, g_part);

    k_init_v<<<256, 256>>>(inp, W_in, b_in);            // + bn0 stats partials (nblk=256)
    k_zero<<<1024, 256>>>(f, 2 * 2048 * 64);

    int nblk_v = 256;                                   // producer of v-stats partials
    for (int i = 0; i < 5; i++) {
        // vertex -> face
        k_stats_final<<<1, 256>>>(rng0 + i * 64, rnbe0 + i * 64, 1.f / 2048.f, nblk_v);
        k_xform<<<128, 256>>>(v, rnW0 + i * 4096, rnb0 + i * 64, X, 2048);
        k_gemm<<<dim3(16, 16, 2), 128>>>(Di, X, part, 8192, 4096);
        k_reduce<<<256, 256>>>((float4*)f, (const float4*)part, 65536, 16);   // + bn1 stats
        // face -> vertex
        k_stats_final<<<1, 256>>>(rng1 + i * 64, rnbe1 + i * 64, 1.f / 4096.f, 256);
        k_xform<<<256, 256>>>(f, rnW1 + i * 4096, rnb1 + i * 64, Y, 4096);
        k_gemm<<<dim3(32, 8, 2), 128>>>(DiA, Y, part, 4096, 8192);
        k_reduce<<<128, 256>>>((float4*)v, (const float4*)part, 32768, 32);   // + next v stats
        nblk_v = 128;
    }

    // epilogue
    k_stats_final<<<1, 256>>>(bn2g, bn2b, 1.f / 2048.f, nblk_v);
    k_xform<<<128, 256>>>(v, W2, b2, Y, 2048);
    k_pool<<<2, 256>>>(Y, mask);
    k_head<<<1, 32>>>(Wfc, bfc, out);
}

// round 5
// speedup vs baseline: 1.3038x; 1.0331x over previous
#include <cuda_runtime.h>
#include <math.h>

typedef unsigned long long ULL;

// ---------------- static scratch (no allocations allowed) ----------------
__device__ __align__(16) float g_v[2 * 1024 * 64];      // vertex feats [B,N,64]
__device__ __align__(16) float g_f[2 * 2048 * 64];      // face feats   [B,F,64]
__device__ __align__(16) float g_X[2 * 4096 * 16];      // x buffer
__device__ __align__(16) float g_Y[2 * 8192 * 16];      // y buffer
__device__ __align__(16) float g_part[4194304];         // split-K partials (16 MB)
__device__ float g_sp[256 * 64];
__device__ float g_sq[256 * 64];
__device__ float g_pool[2 * 64];

// ---------------- helpers ----------------
__device__ __forceinline__ float elu1(float x) { return x > 0.f ? x : expm1f(x); }

__device__ __forceinline__ ULL pk2(float s) {
    ULL r; asm("mov.b64 %0, {%1, %1};" : "=l"(r) : "f"(s)); return r;
}
__device__ __forceinline__ void fma2(ULL& d, ULL a, ULL b) {
    asm("fma.rn.f32x2 %0, %1, %2, %0;" : "+l"(d) : "l"(a), "l"(b));
}

// ---------------- init: v = inp@Win + b, fused elu-stats partials ----------------
__global__ void __launch_bounds__(256) k_init_v(const float* __restrict__ inp,
                                                const float* __restrict__ Win,
                                                const float* __restrict__ bin) {
    __shared__ float ss[256], qq[256];
    int tid = threadIdx.x, ch = tid & 63;
    float b = bin[ch], w0 = Win[ch], w1 = Win[64 + ch], w2 = Win[128 + ch];
    float s = 0.f, q = 0.f;
#pragma unroll
    for (int e = 0; e < 2; e++) {
        int idx = e * 65536 + blockIdx.x * 256 + tid;    // 256 blocks cover 131072
        int r = idx >> 6;
        float acc = fmaf(inp[r * 3 + 2], w2, fmaf(inp[r * 3 + 1], w1, fmaf(inp[r * 3], w0, b)));
        g_v[idx] = acc;
        float x = elu1(acc); s += x; q += x * x;
    }
    ss[tid] = s; qq[tid] = q;
    __syncthreads();
    if (tid < 64) {
#pragma unroll
        for (int j = 1; j < 4; j++) { s += ss[tid + 64 * j]; q += qq[tid + 64 * j]; }
        g_sp[blockIdx.x * 64 + tid] = s;
        g_sq[blockIdx.x * 64 + tid] = q;
    }
}

__global__ void k_zero(float* __restrict__ p, int n) {
    int i = blockIdx.x * 256 + threadIdx.x;
    if (i < n) p[i] = 0.f;
}

// ---------------- elu -> BN -> 64x64 linear -> elu, BN coefs fused in ----------------
// grid = rows/16, 256 threads. Each block: 16 rows, 4 outputs per thread.
__global__ void __launch_bounds__(256) k_xform(const float* __restrict__ src,
                                               const float* __restrict__ W,
                                               const float* __restrict__ bias,
                                               const float* __restrict__ gamma,
                                               const float* __restrict__ beta,
                                               float invc, int nblk,
                                               float* __restrict__ dst) {
    __shared__ float Ws[64 * 64];
    __shared__ float ts[16][64];
    __shared__ float sa[64], sc[64];
    __shared__ float rs[256], rq[256];
    int tid = threadIdx.x;
    int ch = tid & 63, grp = tid >> 6;

    // BN coefficients (redundant per block, from partials)
    float s = 0.f, q = 0.f;
    for (int i = grp; i < nblk; i += 4) { s += g_sp[i * 64 + ch]; q += g_sq[i * 64 + ch]; }
    rs[tid] = s; rq[tid] = q;
    for (int i = tid; i < 4096; i += 256) Ws[i] = W[i];
    __syncthreads();
    if (tid < 64) {
#pragma unroll
        for (int j = 1; j < 4; j++) { s += rs[tid + 64 * j]; q += rq[tid + 64 * j]; }
        float m = s * invc;
        float var = q * invc - m * m;
        float a = gamma[tid] * rsqrtf(var + 1e-5f);
        sa[tid] = a;
        sc[tid] = beta[tid] - m * a;
    }
    __syncthreads();

    float a = sa[ch], c = sc[ch], bb = bias[ch];
    size_t base = (size_t)blockIdx.x * 1024;             // 16 rows * 64
#pragma unroll
    for (int j = 0; j < 4; j++) {
        float x = elu1(src[base + tid + 256 * j]);
        ts[grp + 4 * j][ch] = fmaf(x, a, c);
    }
    __syncthreads();
    float acc[4] = {bb, bb, bb, bb};
#pragma unroll
    for (int k = 0; k < 64; k++) {
        float w = Ws[k * 64 + ch];
#pragma unroll
        for (int j = 0; j < 4; j++) acc[j] = fmaf(ts[grp + 4 * j][k], w, acc[j]);
    }
#pragma unroll
    for (int j = 0; j < 4; j++) dst[base + tid + 256 * j] = elu1(acc[j]);
}

// ---------------- skinny GEMM: part[slice] = D[512-row tile, K-slice] @ X ----------------
// grid (ksplit, M/512, B), block 128. Thread owns 4 CONSECUTIVE rows (4*tid..+3):
// per-k D read = one LDS.128. Staging k-major stride 516 -> STS conflict-free,
// LDS.128 conflict-free. Register-pipelined LDG, double-buffered, 1 barrier/chunk.
__global__ void __launch_bounds__(128) k_gemm(const float* __restrict__ D,
                                              const float* __restrict__ X,
                                              float* __restrict__ part,
                                              int M, int K) {
    __shared__ __align__(16) float Ds[2][8 * 516];       // 33 KB
    __shared__ __align__(16) float Xs[2][8 * 16];        // 1 KB
    int tid = threadIdx.x;
    int slice = blockIdx.x, mt = blockIdx.y, b = blockIdx.z;
    int Kslice = K / gridDim.x;                          // 256
    int nchunk = Kslice >> 3;                            // 32
    const float* Dg = D + ((size_t)b * M + (size_t)mt * 512) * K + (size_t)slice * Kslice;
    const float* Xg = X + ((size_t)b * K + (size_t)slice * Kslice) * 16;

    float4 st[8];
    float4 xst = make_float4(0.f, 0.f, 0.f, 0.f);

    ULL acc[4][8];
#pragma unroll
    for (int j = 0; j < 4; j++)
#pragma unroll
        for (int q = 0; q < 8; q++) acc[j][q] = 0ULL;

    // stage chunk 0
#pragma unroll
    for (int j = 0; j < 8; j++) {
        int i = tid + 128 * j;
        int row = i >> 1, half = i & 1;
        st[j] = *(const float4*)(Dg + (size_t)row * K + half * 4);
    }
    if (tid < 32) xst = *(const float4*)(Xg + tid * 4);
#pragma unroll
    for (int j = 0; j < 8; j++) {
        int i = tid + 128 * j;
        int row = i >> 1, half = i & 1;
        Ds[0][(half * 4 + 0) * 516 + row] = st[j].x;
        Ds[0][(half * 4 + 1) * 516 + row] = st[j].y;
        Ds[0][(half * 4 + 2) * 516 + row] = st[j].z;
        Ds[0][(half * 4 + 3) * 516 + row] = st[j].w;
    }
    if (tid < 32) *(float4*)&Xs[0][tid * 4] = xst;
    __syncthreads();

    for (int c = 0; c < nchunk; c++) {
        // prefetch next chunk into registers
        if (c + 1 < nchunk) {
#pragma unroll
            for (int j = 0; j < 8; j++) {
                int i = tid + 128 * j;
                int row = i >> 1, half = i & 1;
                st[j] = *(const float4*)(Dg + (size_t)row * K + (c + 1) * 8 + half * 4);
            }
            if (tid < 32) xst = *(const float4*)(Xg + (c + 1) * 128 + tid * 4);
        }
        // compute chunk c
        int buf = c & 1;
#pragma unroll
        for (int kk = 0; kk < 8; kk++) {
            const ulonglong2* xr = (const ulonglong2*)&Xs[buf][kk * 16];
            ulonglong2 x0 = xr[0], x1 = xr[1], x2 = xr[2], x3 = xr[3];
            float4 d = *(const float4*)&Ds[buf][kk * 516 + 4 * tid];
            ULL w0 = pk2(d.x), w1 = pk2(d.y), w2 = pk2(d.z), w3 = pk2(d.w);
            fma2(acc[0][0], w0, x0.x); fma2(acc[0][1], w0, x0.y);
            fma2(acc[0][2], w0, x1.x); fma2(acc[0][3], w0, x1.y);
            fma2(acc[0][4], w0, x2.x); fma2(acc[0][5], w0, x2.y);
            fma2(acc[0][6], w0, x3.x); fma2(acc[0][7], w0, x3.y);
            fma2(acc[1][0], w1, x0.x); fma2(acc[1][1], w1, x0.y);
            fma2(acc[1][2], w1, x1.x); fma2(acc[1][3], w1, x1.y);
            fma2(acc[1][4], w1, x2.x); fma2(acc[1][5], w1, x2.y);
            fma2(acc[1][6], w1, x3.x); fma2(acc[1][7], w1, x3.y);
            fma2(acc[2][0], w2, x0.x); fma2(acc[2][1], w2, x0.y);
            fma2(acc[2][2], w2, x1.x); fma2(acc[2][3], w2, x1.y);
            fma2(acc[2][4], w2, x2.x); fma2(acc[2][5], w2, x2.y);
            fma2(acc[2][6], w2, x3.x); fma2(acc[2][7], w2, x3.y);
            fma2(acc[3][0], w3, x0.x); fma2(acc[3][1], w3, x0.y);
            fma2(acc[3][2], w3, x1.x); fma2(acc[3][3], w3, x1.y);
            fma2(acc[3][4], w3, x2.x); fma2(acc[3][5], w3, x2.y);
            fma2(acc[3][6], w3, x3.x); fma2(acc[3][7], w3, x3.y);
        }
        // stage next chunk into the other buffer
        if (c + 1 < nchunk) {
            int nb = buf ^ 1;
#pragma unroll
            for (int j = 0; j < 8; j++) {
                int i = tid + 128 * j;
                int row = i >> 1, half = i & 1;
                Ds[nb][(half * 4 + 0) * 516 + row] = st[j].x;
                Ds[nb][(half * 4 + 1) * 516 + row] = st[j].y;
                Ds[nb][(half * 4 + 2) * 516 + row] = st[j].z;
                Ds[nb][(half * 4 + 3) * 516 + row] = st[j].w;
            }
            if (tid < 32) *(float4*)&Xs[nb][tid * 4] = xst;
            __syncthreads();
        }
    }

    size_t obase = ((size_t)slice * gridDim.z + b) * M + (size_t)mt * 512 + 4 * tid;
#pragma unroll
    for (int j = 0; j < 4; j++) {
        ulonglong2* op = (ulonglong2*)(part + (obase + j) * 16);
#pragma unroll
        for (int q = 0; q < 4; q++) {
            ulonglong2 t; t.x = acc[j][2 * q]; t.y = acc[j][2 * q + 1];
            op[q] = t;
        }
    }
}

// ---------------- split-K reduce + fused elu-stats partials ----------------
__global__ void __launch_bounds__(256) k_reduce(float4* __restrict__ out,
                                                const float4* __restrict__ part,
                                                int n4, int ksplit) {
    __shared__ float ss[256 * 4], qq[256 * 4];
    int tid = threadIdx.x;
    int i = blockIdx.x * 256 + tid;
    float4 a = out[i];
    for (int s = 0; s < ksplit; s++) {
        float4 p = part[(size_t)s * n4 + i];
        a.x += p.x; a.y += p.y; a.z += p.z; a.w += p.w;
    }
    out[i] = a;
    float e0 = elu1(a.x), e1 = elu1(a.y), e2 = elu1(a.z), e3 = elu1(a.w);
    ss[tid * 4 + 0] = e0; qq[tid * 4 + 0] = e0 * e0;
    ss[tid * 4 + 1] = e1; qq[tid * 4 + 1] = e1 * e1;
    ss[tid * 4 + 2] = e2; qq[tid * 4 + 2] = e2 * e2;
    ss[tid * 4 + 3] = e3; qq[tid * 4 + 3] = e3 * e3;
    __syncthreads();
    if (tid < 64) {
        int g = tid >> 2, e = tid & 3;                  // channel = 4*g + e
        float s = 0.f, q = 0.f;
#pragma unroll
        for (int m = 0; m < 16; m++) {
            int t = g + 16 * m;
            s += ss[t * 4 + e]; q += qq[t * 4 + e];
        }
        g_sp[blockIdx.x * 64 + tid] = s;
        g_sq[blockIdx.x * 64 + tid] = q;
    }
}

// ---------------- epilogue ----------------
__global__ void k_pool(const float* __restrict__ t, const float* __restrict__ mask) {
    __shared__ float ss[256], ms[256];
    int b = blockIdx.x;
    int ch = threadIdx.x & 63, g = threadIdx.x >> 6;
    float s = 0.f, m = 0.f;
    for (int n = g; n < 1024; n += 4) {
        float mv = mask[b * 1024 + n];
        s += t[((size_t)b * 1024 + n) * 64 + ch] * mv;
        m += mv;
    }
    ss[threadIdx.x] = s; ms[threadIdx.x] = m;
    __syncthreads();
    if (g == 0) {
#pragma unroll
        for (int j = 1; j < 4; j++) { s += ss[ch + 64 * j]; m += ms[ch + 64 * j]; }
        g_pool[b * 64 + ch] = s / m;
    }
}

__global__ void k_head(const float* __restrict__ Wfc, const float* __restrict__ bfc,
                       float* __restrict__ out) {
    __shared__ float lg[2][10];
    int tid = threadIdx.x;
    if (tid < 20) {
        int b = tid / 10, j = tid % 10;
        float acc = bfc[j];
        for (int ch = 0; ch < 64; ch++) acc = fmaf(g_pool[b * 64 + ch], Wfc[ch * 10 + j], acc);
        lg[b][j] = acc;
    }
    __syncthreads();
    if (tid < 20) {
        int b = tid / 10, j = tid % 10;
        float mx = -1e30f;
        for (int t = 0; t < 10; t++) mx = fmaxf(mx, lg[b][t]);
        float se = 0.f;
        for (int t = 0; t < 10; t++) se += expf(lg[b][t] - mx);
        out[b * 10 + j] = lg[b][j] - mx - logf(se);
    }
}

// ---------------- launcher ----------------
extern "C" void kernel_launch(void* const* d_in, const int* in_sizes, int n_in,
                              void* d_out, int out_size) {
    const float* inp  = (const float*)d_in[0];
    const float* Di   = (const float*)d_in[1];
    const float* DiA  = (const float*)d_in[2];
    const float* mask = (const float*)d_in[3];
    const float* W_in = (const float*)d_in[4];
    const float* b_in = (const float*)d_in[5];
    const float* rnW0 = (const float*)d_in[6];
    const float* rnb0 = (const float*)d_in[7];
    const float* rng0 = (const float*)d_in[8];
    const float* rnbe0= (const float*)d_in[9];
    const float* rnW1 = (const float*)d_in[10];
    const float* rnb1 = (const float*)d_in[11];
    const float* rng1 = (const float*)d_in[12];
    const float* rnbe1= (const float*)d_in[13];
    const float* bn2g = (const float*)d_in[14];
    const float* bn2b = (const float*)d_in[15];
    const float* W2   = (const float*)d_in[16];
    const float* b2   = (const float*)d_in[17];
    const float* Wfc  = (const float*)d_in[18];
    const float* bfc  = (const float*)d_in[19];
    float* out = (float*)d_out;

    float *v, *f, *X, *Y, *part;
    cudaGetSymbolAddress((void**)&v, g_v);
    cudaGetSymbolAddress((void**)&f, g_f);
    cudaGetSymbolAddress((void**)&X, g_X);
    cudaGetSymbolAddress((void**)&Y, g_Y);
    cudaGetSymbolAddress((void**)&part, g_part);

    k_init_v<<<256, 256>>>(inp, W_in, b_in);             // #1  (v + bn stats partials)
    k_zero<<<1024, 256>>>(f, 2 * 2048 * 64);             // #2

    int nblk_v = 256;
    for (int i = 0; i < 5; i++) {
        // vertex -> face
        k_xform<<<128, 256>>>(v, rnW0 + i * 4096, rnb0 + i * 64,
                              rng0 + i * 64, rnbe0 + i * 64,
                              1.f / 2048.f, nblk_v, X);  // #3 (gemm is #4 for ncu)
        k_gemm<<<dim3(16, 16, 2), 128>>>(Di, X, part, 8192, 4096);
        k_reduce<<<256, 256>>>((float4*)f, (const float4*)part, 65536, 16);
        // face -> vertex
        k_xform<<<256, 256>>>(f, rnW1 + i * 4096, rnb1 + i * 64,
                              rng1 + i * 64, rnbe1 + i * 64,
                              1.f / 4096.f, 256, Y);
        k_gemm<<<dim3(32, 8, 2), 128>>>(DiA, Y, part, 4096, 8192);
        k_reduce<<<128, 256>>>((float4*)v, (const float4*)part, 32768, 32);
        nblk_v = 128;
    }

    // epilogue
    k_xform<<<128, 256>>>(v, W2, b2, bn2g, bn2b, 1.f / 2048.f, nblk_v, Y);
    k_pool<<<2, 256>>>(Y, mask);
    k_head<<<1, 32>>>(Wfc, bfc, out);
}

// round 6
// speedup vs baseline: 1.7135x; 1.3142x over previous
#include <cuda_runtime.h>
#include <math.h>

typedef unsigned long long ULL;

// ---------------- static scratch (no allocations allowed) ----------------
__device__ __align__(16) float g_v[2 * 1024 * 64];      // vertex feats [B,N,64]
__device__ __align__(16) float g_f[2 * 2048 * 64];      // face feats   [B,F,64]
__device__ __align__(16) float g_X[2 * 4096 * 16];      // x buffer
__device__ __align__(16) float g_Y[2 * 8192 * 16];      // y buffer
__device__ __align__(16) float g_part[4194304];         // split-K partials (16 MB)
__device__ float g_sp[256 * 64];
__device__ float g_sq[256 * 64];
__device__ float g_pool[2 * 64];

// ---------------- helpers ----------------
__device__ __forceinline__ float elu1(float x) { return x > 0.f ? x : expm1f(x); }

__device__ __forceinline__ ULL pk2(float s) {
    ULL r; asm("mov.b64 %0, {%1, %1};" : "=l"(r) : "f"(s)); return r;
}
__device__ __forceinline__ void fma2(ULL& d, ULL a, ULL b) {
    asm("fma.rn.f32x2 %0, %1, %2, %0;" : "+l"(d) : "l"(a), "l"(b));
}
__device__ __forceinline__ void cpa8(unsigned dst, const float* src) {
    asm volatile("cp.async.ca.shared.global [%0], [%1], 8;" :: "r"(dst), "l"(src));
}

// ---------------- init: v = inp@Win + b, fused elu-stats partials ----------------
__global__ void __launch_bounds__(256) k_init_v(const float* __restrict__ inp,
                                                const float* __restrict__ Win,
                                                const float* __restrict__ bin) {
    __shared__ float ss[256], qq[256];
    int tid = threadIdx.x, ch = tid & 63;
    float b = bin[ch], w0 = Win[ch], w1 = Win[64 + ch], w2 = Win[128 + ch];
    float s = 0.f, q = 0.f;
#pragma unroll
    for (int e = 0; e < 2; e++) {
        int idx = e * 65536 + blockIdx.x * 256 + tid;    // 256 blocks cover 131072
        int r = idx >> 6;
        float acc = fmaf(inp[r * 3 + 2], w2, fmaf(inp[r * 3 + 1], w1, fmaf(inp[r * 3], w0, b)));
        g_v[idx] = acc;
        float x = elu1(acc); s += x; q += x * x;
    }
    ss[tid] = s; qq[tid] = q;
    __syncthreads();
    if (tid < 64) {
#pragma unroll
        for (int j = 1; j < 4; j++) { s += ss[tid + 64 * j]; q += qq[tid + 64 * j]; }
        g_sp[blockIdx.x * 64 + tid] = s;
        g_sq[blockIdx.x * 64 + tid] = q;
    }
}

__global__ void k_zero(float* __restrict__ p, int n) {
    int i = blockIdx.x * 256 + threadIdx.x;
    if (i < n) p[i] = 0.f;
}

// ---------------- elu -> BN -> 64x64 linear -> elu, BN coefs fused in ----------------
__global__ void __launch_bounds__(256) k_xform(const float* __restrict__ src,
                                               const float* __restrict__ W,
                                               const float* __restrict__ bias,
                                               const float* __restrict__ gamma,
                                               const float* __restrict__ beta,
                                               float invc, int nblk,
                                               float* __restrict__ dst) {
    __shared__ float Ws[64 * 64];
    __shared__ float ts[16][64];
    __shared__ float sa[64], sc[64];
    __shared__ float rs[256], rq[256];
    int tid = threadIdx.x;
    int ch = tid & 63, grp = tid >> 6;

    float s = 0.f, q = 0.f;
    for (int i = grp; i < nblk; i += 4) { s += g_sp[i * 64 + ch]; q += g_sq[i * 64 + ch]; }
    rs[tid] = s; rq[tid] = q;
    for (int i = tid; i < 4096; i += 256) Ws[i] = W[i];
    __syncthreads();
    if (tid < 64) {
#pragma unroll
        for (int j = 1; j < 4; j++) { s += rs[tid + 64 * j]; q += rq[tid + 64 * j]; }
        float m = s * invc;
        float var = q * invc - m * m;
        float a = gamma[tid] * rsqrtf(var + 1e-5f);
        sa[tid] = a;
        sc[tid] = beta[tid] - m * a;
    }
    __syncthreads();

    float a = sa[ch], c = sc[ch], bb = bias[ch];
    size_t base = (size_t)blockIdx.x * 1024;             // 16 rows * 64
#pragma unroll
    for (int j = 0; j < 4; j++) {
        float x = elu1(src[base + tid + 256 * j]);
        ts[grp + 4 * j][ch] = fmaf(x, a, c);
    }
    __syncthreads();
    float acc[4] = {bb, bb, bb, bb};
#pragma unroll
    for (int k = 0; k < 64; k++) {
        float w = Ws[k * 64 + ch];
#pragma unroll
        for (int j = 0; j < 4; j++) acc[j] = fmaf(ts[grp + 4 * j][k], w, acc[j]);
    }
#pragma unroll
    for (int j = 0; j < 4; j++) dst[base + tid + 256 * j] = elu1(acc[j]);
}

// ---------------- skinny GEMM: part[slice] = D[256-row tile, K-slice] @ X ----------------
// grid (ksplit, M/256, B), block 128, ~5 CTAs/SM. cp.async(8B) staging of D into
// k-minor smem rows of stride 18 floats (72B): per-k LDS across 16 consecutive
// rows hits banks 18r mod 32 -> all distinct (conflict-free). Thread owns 4 rows
// x 8 cols (16 fma2 per k). Double-buffered 16-k chunks.
__global__ void __launch_bounds__(128, 5) k_gemm(const float* __restrict__ D,
                                                 const float* __restrict__ X,
                                                 float* __restrict__ part,
                                                 int M, int K) {
    __shared__ __align__(16) float Ds[2][256 * 18];      // 36.9 KB
    __shared__ __align__(16) float Xs[2][16 * 16];       // 2 KB
    const int tid = threadIdx.x;
    const int slice = blockIdx.x, mt = blockIdx.y, b = blockIdx.z;
    const int Kslice = K / gridDim.x;                    // 256
    const int nch = Kslice >> 4;                         // 16
    const float* Dg = D + ((size_t)b * M + (size_t)mt * 256) * K + (size_t)slice * Kslice;
    const float* Xg = X + ((size_t)b * K + (size_t)slice * Kslice) * 16;

    unsigned ds0 = (unsigned)__cvta_generic_to_shared(&Ds[0][0]);
    unsigned ds1 = (unsigned)__cvta_generic_to_shared(&Ds[1][0]);
    unsigned xs0 = (unsigned)__cvta_generic_to_shared(&Xs[0][0]);
    unsigned xs1 = (unsigned)__cvta_generic_to_shared(&Xs[1][0]);

    const int gr = tid >> 3, gq = tid & 7;               // staging: row base, 8B granule

    ULL acc[4][4];
#pragma unroll
    for (int j = 0; j < 4; j++)
#pragma unroll
        for (int q = 0; q < 4; q++) acc[j][q] = 0ULL;

    // issue chunk c into buffer buf
    auto issue = [&](int c, unsigned dsb, unsigned xsb) {
        const float* dsrc = Dg + c * 16 + gq * 2;
#pragma unroll
        for (int j = 0; j < 16; j++) {
            int r = gr + 16 * j;
            cpa8(dsb + (unsigned)(r * 18 + gq * 2) * 4, dsrc + (size_t)r * K);
        }
        cpa8(xsb + (unsigned)tid * 8, Xg + c * 256 + tid * 2);
        asm volatile("cp.async.commit_group;");
    };

    issue(0, ds0, xs0);

    const int h = tid & 1, rl = tid >> 1;                // compute: 4 rows, 8 cols
    const int dbase = rl * 18;

    for (int c = 0; c < nch; c++) {
        if (c + 1 < nch) {
            issue(c + 1, (c & 1) ? ds0 : ds1, (c & 1) ? xs0 : xs1);
            asm volatile("cp.async.wait_group 1;");
        } else {
            asm volatile("cp.async.wait_group 0;");
        }
        __syncthreads();
        const float* dsm = Ds[c & 1];
        const float* xsm = Xs[c & 1];
#pragma unroll
        for (int kk = 0; kk < 16; kk++) {
            const ulonglong2* xr = (const ulonglong2*)&xsm[kk * 16 + h * 8];
            ulonglong2 xa = xr[0], xb = xr[1];
#pragma unroll
            for (int j = 0; j < 4; j++) {
                float dv = dsm[dbase + 1152 * j + kk];   // (rl + 64j)*18 + kk
                ULL w = pk2(dv);
                fma2(acc[j][0], w, xa.x); fma2(acc[j][1], w, xa.y);
                fma2(acc[j][2], w, xb.x); fma2(acc[j][3], w, xb.y);
            }
        }
        __syncthreads();
    }

    size_t obase = ((size_t)slice * gridDim.z + b) * M + (size_t)mt * 256;
#pragma unroll
    for (int j = 0; j < 4; j++) {
        ulonglong2* op = (ulonglong2*)(part + (obase + rl + 64 * j) * 16 + h * 8);
        ulonglong2 t0; t0.x = acc[j][0]; t0.y = acc[j][1];
        ulonglong2 t1; t1.x = acc[j][2]; t1.y = acc[j][3];
        op[0] = t0; op[1] = t1;
    }
}

// ---------------- split-K reduce + fused elu-stats partials ----------------
__global__ void __launch_bounds__(256) k_reduce(float4* __restrict__ out,
                                                const float4* __restrict__ part,
                                                int n4, int ksplit) {
    __shared__ float ss[256 * 4], qq[256 * 4];
    int tid = threadIdx.x;
    int i = blockIdx.x * 256 + tid;
    float4 a = out[i];
    for (int s = 0; s < ksplit; s++) {
        float4 p = part[(size_t)s * n4 + i];
        a.x += p.x; a.y += p.y; a.z += p.z; a.w += p.w;
    }
    out[i] = a;
    float e0 = elu1(a.x), e1 = elu1(a.y), e2 = elu1(a.z), e3 = elu1(a.w);
    ss[tid * 4 + 0] = e0; qq[tid * 4 + 0] = e0 * e0;
    ss[tid * 4 + 1] = e1; qq[tid * 4 + 1] = e1 * e1;
    ss[tid * 4 + 2] = e2; qq[tid * 4 + 2] = e2 * e2;
    ss[tid * 4 + 3] = e3; qq[tid * 4 + 3] = e3 * e3;
    __syncthreads();
    if (tid < 64) {
        int g = tid >> 2, e = tid & 3;                  // channel = 4*g + e
        float s = 0.f, q = 0.f;
#pragma unroll
        for (int m = 0; m < 16; m++) {
            int t = g + 16 * m;
            s += ss[t * 4 + e]; q += qq[t * 4 + e];
        }
        g_sp[blockIdx.x * 64 + tid] = s;
        g_sq[blockIdx.x * 64 + tid] = q;
    }
}

// ---------------- epilogue ----------------
__global__ void k_pool(const float* __restrict__ t, const float* __restrict__ mask) {
    __shared__ float ss[256], ms[256];
    int b = blockIdx.x;
    int ch = threadIdx.x & 63, g = threadIdx.x >> 6;
    float s = 0.f, m = 0.f;
    for (int n = g; n < 1024; n += 4) {
        float mv = mask[b * 1024 + n];
        s += t[((size_t)b * 1024 + n) * 64 + ch] * mv;
        m += mv;
    }
    ss[threadIdx.x] = s; ms[threadIdx.x] = m;
    __syncthreads();
    if (g == 0) {
#pragma unroll
        for (int j = 1; j < 4; j++) { s += ss[ch + 64 * j]; m += ms[ch + 64 * j]; }
        g_pool[b * 64 + ch] = s / m;
    }
}

__global__ void k_head(const float* __restrict__ Wfc, const float* __restrict__ bfc,
                       float* __restrict__ out) {
    __shared__ float lg[2][10];
    int tid = threadIdx.x;
    if (tid < 20) {
        int b = tid / 10, j = tid % 10;
        float acc = bfc[j];
        for (int ch = 0; ch < 64; ch++) acc = fmaf(g_pool[b * 64 + ch], Wfc[ch * 10 + j], acc);
        lg[b][j] = acc;
    }
    __syncthreads();
    if (tid < 20) {
        int b = tid / 10, j = tid % 10;
        float mx = -1e30f;
        for (int t = 0; t < 10; t++) mx = fmaxf(mx, lg[b][t]);
        float se = 0.f;
        for (int t = 0; t < 10; t++) se += expf(lg[b][t] - mx);
        out[b * 10 + j] = lg[b][j] - mx - logf(se);
    }
}

// ---------------- launcher ----------------
extern "C" void kernel_launch(void* const* d_in, const int* in_sizes, int n_in,
                              void* d_out, int out_size) {
    const float* inp  = (const float*)d_in[0];
    const float* Di   = (const float*)d_in[1];
    const float* DiA  = (const float*)d_in[2];
    const float* mask = (const float*)d_in[3];
    const float* W_in = (const float*)d_in[4];
    const float* b_in = (const float*)d_in[5];
    const float* rnW0 = (const float*)d_in[6];
    const float* rnb0 = (const float*)d_in[7];
    const float* rng0 = (const float*)d_in[8];
    const float* rnbe0= (const float*)d_in[9];
    const float* rnW1 = (const float*)d_in[10];
    const float* rnb1 = (const float*)d_in[11];
    const float* rng1 = (const float*)d_in[12];
    const float* rnbe1= (const float*)d_in[13];
    const float* bn2g = (const float*)d_in[14];
    const float* bn2b = (const float*)d_in[15];
    const float* W2   = (const float*)d_in[16];
    const float* b2   = (const float*)d_in[17];
    const float* Wfc  = (const float*)d_in[18];
    const float* bfc  = (const float*)d_in[19];
    float* out = (float*)d_out;

    float *v, *f, *X, *Y, *part;
    cudaGetSymbolAddress((void**)&v, g_v);
    cudaGetSymbolAddress((void**)&f, g_f);
    cudaGetSymbolAddress((void**)&X, g_X);
    cudaGetSymbolAddress((void**)&Y, g_Y);
    cudaGetSymbolAddress((void**)&part, g_part);

    k_init_v<<<256, 256>>>(inp, W_in, b_in);             // #1  (v + bn stats partials)
    k_zero<<<1024, 256>>>(f, 2 * 2048 * 64);             // #2

    int nblk_v = 256;
    for (int i = 0; i < 5; i++) {
        // vertex -> face
        k_xform<<<128, 256>>>(v, rnW0 + i * 4096, rnb0 + i * 64,
                              rng0 + i * 64, rnbe0 + i * 64,
                              1.f / 2048.f, nblk_v, X);  // #3 (gemm is #4 for ncu)
        k_gemm<<<dim3(16, 32, 2), 128>>>(Di, X, part, 8192, 4096);
        k_reduce<<<256, 256>>>((float4*)f, (const float4*)part, 65536, 16);
        // face -> vertex
        k_xform<<<256, 256>>>(f, rnW1 + i * 4096, rnb1 + i * 64,
                              rng1 + i * 64, rnbe1 + i * 64,
                              1.f / 4096.f, 256, Y);
        k_gemm<<<dim3(32, 16, 2), 128>>>(DiA, Y, part, 4096, 8192);
        k_reduce<<<128, 256>>>((float4*)v, (const float4*)part, 32768, 32);
        nblk_v = 128;
    }

    // epilogue
    k_xform<<<128, 256>>>(v, W2, b2, bn2g, bn2b, 1.f / 2048.f, nblk_v, Y);
    k_pool<<<2, 256>>>(Y, mask);
    k_head<<<1, 32>>>(Wfc, bfc, out);
}